// round 16
// baseline (speedup 1.0000x reference)
#include <cuda_runtime.h>
#include <cuda_bf16.h>
#include <cstdint>

typedef unsigned int u32;

#define BB 4
#define TT 2048
#define DDIM 512
#define HH 8
#define DKH 64

#define SZQ ((size_t)BB * HH * TT * DKH)   // 4,194,304
#define SZX ((size_t)BB * TT * DDIM)       // 4,194,304

// ---------------- scratch (__device__ globals; no allocation) ----------------
__device__ float g_q[SZQ];                        // [B,H,T,DK] fp32
__device__ float g_k[SZQ];                        // [B,H,T,DK] fp32
__device__ float g_vt[SZQ];                       // [B,H,DK,T] fp32 (transposed)
__device__ float g_ctx[SZX];                      // [B,T,D] fp32
__device__ u32 g_mbits[(size_t)BB * TT * (TT / 32)];  // packed mask bits

// ---------------- helpers ----------------
__device__ __forceinline__ u32 smem_u32(const void* p) {
    u32 a;
    asm("{ .reg .u64 t; cvta.to.shared.u64 t, %1; cvt.u32.u64 %0, t; }" : "=r"(a) : "l"(p));
    return a;
}
__device__ __forceinline__ void split_hl(float v, __nv_bfloat16& h, __nv_bfloat16& l) {
    h = __float2bfloat16(v);
    l = __float2bfloat16(v - __bfloat162float(h));
}
__device__ __forceinline__ u32 pack2(__nv_bfloat16 a, __nv_bfloat16 b) {
    return (u32)__bfloat16_as_ushort(a) | ((u32)__bfloat16_as_ushort(b) << 16);
}
__device__ __forceinline__ void ldsm_x4(u32& r0, u32& r1, u32& r2, u32& r3, u32 addr) {
    asm volatile("ldmatrix.sync.aligned.m8n8.x4.shared.b16 {%0,%1,%2,%3}, [%4];"
                 : "=r"(r0), "=r"(r1), "=r"(r2), "=r"(r3) : "r"(addr));
}
__device__ __forceinline__ void mma16816(float* c, const u32* a, u32 b0, u32 b1) {
    asm volatile(
        "mma.sync.aligned.m16n8k16.row.col.f32.bf16.bf16.f32 "
        "{%0,%1,%2,%3}, {%4,%5,%6,%7}, {%8,%9}, {%0,%1,%2,%3};"
        : "+f"(c[0]), "+f"(c[1]), "+f"(c[2]), "+f"(c[3])
        : "r"(a[0]), "r"(a[1]), "r"(a[2]), "r"(a[3]), "r"(b0), "r"(b1));
}

// fp32 source [rows][ld] -> bf16 hi/lo smem tiles. W4 float4-groups per row.
// (combined load+split+store; used for loop-invariant Q preload)
template <int ROWS, int W4, int STRIDE>
__device__ __forceinline__ void load_f32_hl(
    __nv_bfloat16 (*sh)[STRIDE], __nv_bfloat16 (*sl)[STRIDE],
    const float* __restrict__ g, size_t ld, size_t row0, int k0, int tid)
{
    #pragma unroll
    for (int i = tid; i < ROWS * W4; i += 256) {
        int r = i / W4, c = i % W4;
        float4 v = *(const float4*)&g[(row0 + (size_t)r) * ld + k0 + c * 4];
        __nv_bfloat16 h0, l0, h1, l1, h2, l2, h3, l3;
        split_hl(v.x, h0, l0); split_hl(v.y, h1, l1);
        split_hl(v.z, h2, l2); split_hl(v.w, h3, l3);
        *(uint2*)&sh[r][c * 4] = make_uint2(pack2(h0, h1), pack2(h2, h3));
        *(uint2*)&sl[r][c * 4] = make_uint2(pack2(l0, l1), pack2(l2, l3));
    }
}

// ---- pipelined loader: LDG fp32 tile -> regs (REG = ROWS*W4/256 float4) ----
template <int ROWS, int W4>
__device__ __forceinline__ void ldg_tile(
    float4 (&reg)[ROWS * W4 / 256],
    const float* __restrict__ g, size_t ld, size_t row0, int k0, int tid)
{
    #pragma unroll
    for (int it = 0; it < ROWS * W4 / 256; it++) {
        int i = tid + it * 256;
        int r = i / W4, c = i % W4;
        reg[it] = *(const float4*)&g[(row0 + (size_t)r) * ld + k0 + c * 4];
    }
}
// ---- split regs to bf16 hi/lo and store to smem ----
template <int ROWS, int W4, int STRIDE>
__device__ __forceinline__ void sts_tile(
    const float4 (&reg)[ROWS * W4 / 256],
    __nv_bfloat16 (*sh)[STRIDE], __nv_bfloat16 (*sl)[STRIDE], int tid)
{
    #pragma unroll
    for (int it = 0; it < ROWS * W4 / 256; it++) {
        int i = tid + it * 256;
        int r = i / W4, c = i % W4;
        float4 v = reg[it];
        __nv_bfloat16 h0, l0, h1, l1, h2, l2, h3, l3;
        split_hl(v.x, h0, l0); split_hl(v.y, h1, l1);
        split_hl(v.z, h2, l2); split_hl(v.w, h3, l3);
        *(uint2*)&sh[r][c * 4] = make_uint2(pack2(h0, h1), pack2(h2, h3));
        *(uint2*)&sl[r][c * 4] = make_uint2(pack2(l0, l1), pack2(l2, l3));
    }
}

// warp-MMA over one 32-wide K slab, bf16x3 emulation (3 MMA terms)
template <int MF, int NF, int AS, int BS>
__device__ __forceinline__ void mma_hl(
    const __nv_bfloat16 (*Ah)[AS], const __nv_bfloat16 (*Al)[AS],
    const __nv_bfloat16 (*Bh)[BS], const __nv_bfloat16 (*Bl)[BS],
    int wrow, int wcol, int lane, int kA, int kB, float acc[MF][NF][4])
{
    const int arow = wrow + (lane & 15);
    const int akh = (lane >> 4) << 3;
    const int brow = wcol + (lane & 7) + ((lane & 16) >> 1);
    const int bkh = (lane & 8);
    #pragma unroll
    for (int ks = 0; ks < 32; ks += 16) {
        u32 ah[MF][4], al[MF][4];
        #pragma unroll
        for (int mf = 0; mf < MF; mf++) {
            ldsm_x4(ah[mf][0], ah[mf][1], ah[mf][2], ah[mf][3],
                    smem_u32(&Ah[arow + mf * 16][kA + ks + akh]));
            ldsm_x4(al[mf][0], al[mf][1], al[mf][2], al[mf][3],
                    smem_u32(&Al[arow + mf * 16][kA + ks + akh]));
        }
        #pragma unroll
        for (int np = 0; np < NF / 2; np++) {
            u32 bh0, bh1, bh2, bh3, bl0, bl1, bl2, bl3;
            ldsm_x4(bh0, bh1, bh2, bh3, smem_u32(&Bh[brow + np * 16][kB + ks + bkh]));
            ldsm_x4(bl0, bl1, bl2, bl3, smem_u32(&Bl[brow + np * 16][kB + ks + bkh]));
            #pragma unroll
            for (int mf = 0; mf < MF; mf++) {
                mma16816(acc[mf][2 * np],     ah[mf], bh0, bh1);
                mma16816(acc[mf][2 * np],     ah[mf], bl0, bl1);
                mma16816(acc[mf][2 * np],     al[mf], bh0, bh1);
                mma16816(acc[mf][2 * np + 1], ah[mf], bh2, bh3);
                mma16816(acc[mf][2 * np + 1], ah[mf], bl2, bl3);
                mma16816(acc[mf][2 * np + 1], al[mf], bh2, bh3);
            }
        }
    }
}

// ---------------- mask bit packing ----------------
__global__ __launch_bounds__(256) void cvt_mask_kernel(const int* __restrict__ mask)
{
    size_t i = (size_t)blockIdx.x * 256 + threadIdx.x;
    u32 bit = (mask[i] != 0) ? 1u : 0u;
    u32 word = __ballot_sync(0xffffffffu, bit);
    if ((threadIdx.x & 31) == 0) g_mbits[i >> 5] = word;
}

// ---------------- proj: out = X @ W^T + b -> q/k fp32 [B,H,T,DK], vt [B,H,DK,T]
// pipelined: LDG(k0+32) in flight during MMA(k0)
__global__ __launch_bounds__(256, 2) void proj_mma(const float* __restrict__ X,
                                                   const float* __restrict__ W,
                                                   const float* __restrict__ bias, int dst)
{
    __shared__ __nv_bfloat16 sAh[128][40], sAl[128][40];
    __shared__ __nv_bfloat16 sBh[128][40], sBl[128][40];
    const int tid = threadIdx.x, lane = tid & 31, wid = tid >> 5;
    const int wrow = (wid >> 1) * 32, wcol = (wid & 1) * 64;
    const int tile_m = blockIdx.y * 128, tile_n = blockIdx.x * 128;

    float4 areg[4], breg[4];
    ldg_tile<128, 8>(areg, X, DDIM, tile_m, 0, tid);
    ldg_tile<128, 8>(breg, W, DDIM, tile_n, 0, tid);

    float acc[2][8][4] = {};
    for (int k0 = 0; k0 < DDIM; k0 += 32) {
        __syncthreads();
        sts_tile<128, 8, 40>(areg, sAh, sAl, tid);
        sts_tile<128, 8, 40>(breg, sBh, sBl, tid);
        __syncthreads();
        if (k0 + 32 < DDIM) {
            ldg_tile<128, 8>(areg, X, DDIM, tile_m, k0 + 32, tid);
            ldg_tile<128, 8>(breg, W, DDIM, tile_n, k0 + 32, tid);
        }
        mma_hl<2, 8, 40, 40>(sAh, sAl, sBh, sBl, wrow, wcol, lane, 0, 0, acc);
    }

    float* dq = (dst == 0) ? g_q : g_k;
    const int r0 = tile_m + wrow + (lane >> 2);
    const int c0 = tile_n + wcol + (lane & 3) * 2;
    #pragma unroll
    for (int mf = 0; mf < 2; mf++)
        #pragma unroll
        for (int hf = 0; hf < 2; hf++) {
            int m = r0 + mf * 16 + hf * 8;
            int b = m >> 11, t = m & (TT - 1);
            #pragma unroll
            for (int nf = 0; nf < 8; nf++) {
                int n = c0 + nf * 8;
                float v0 = acc[mf][nf][hf * 2]     + bias[n];
                float v1 = acc[mf][nf][hf * 2 + 1] + bias[n + 1];
                int hh = n >> 6, dk = n & 63;
                if (dst == 2) {
                    size_t base = ((size_t)(b * HH + hh) * DKH + dk) * TT + t;
                    g_vt[base] = v0;
                    g_vt[base + TT] = v1;
                } else {
                    size_t idx = ((size_t)(b * HH + hh) * TT + t) * DKH + dk;
                    *(float2*)&dq[idx] = make_float2(v0, v1);
                }
            }
        }
}

// ---------------- fused: S=QK^T/8 -> exp/mask -> p(unnorm)->aw ;
// ctx=(p@v)/sum via REGISTER-direct P fragments. Pipelined KV loads.
// grid (16 tile_m, 32 bh), 256 thr, dynamic smem 73728 B
__global__ __launch_bounds__(256, 2) void fused_attn(float* __restrict__ aw)
{
    extern __shared__ __nv_bfloat16 dyn[];
    __nv_bfloat16 (*sQh)[72] = (__nv_bfloat16 (*)[72])(dyn);
    __nv_bfloat16 (*sQl)[72] = (__nv_bfloat16 (*)[72])(dyn + 9216);
    __nv_bfloat16 (*sKh)[72] = (__nv_bfloat16 (*)[72])(dyn + 18432);
    __nv_bfloat16 (*sKl)[72] = (__nv_bfloat16 (*)[72])(dyn + 23040);
    __nv_bfloat16 (*sVh)[72] = (__nv_bfloat16 (*)[72])(dyn + 27648);
    __nv_bfloat16 (*sVl)[72] = (__nv_bfloat16 (*)[72])(dyn + 32256);

    const int tid = threadIdx.x, lane = tid & 31, wid = tid >> 5;
    const int wrow = wid * 16;
    const int tile_m = blockIdx.x * 128;
    const int bz = blockIdx.y;
    const int b = bz >> 3, hh = bz & 7;
    const float* qp = g_q + (size_t)bz * TT * DKH;
    const float* kp = g_k + (size_t)bz * TT * DKH;
    const float* vt = g_vt + (size_t)bz * DKH * TT;

    float4 kreg[4], vreg[4];
    ldg_tile<64, 16>(kreg, kp, DKH, 0, 0, tid);
    ldg_tile<64, 16>(vreg, vt, TT, 0, 0, tid);
    load_f32_hl<128, 16, 72>(sQh, sQl, qp, DKH, tile_m, 0, tid);

    float acc_av[8][4] = {};
    float rs[2] = {0.0f, 0.0f};
    const int rq = (lane >> 2);
    const int cq = (lane & 3) * 2;
    // B-fragment addressing for V (wcol = 0)
    const int brow_v = (lane & 7) + ((lane & 16) >> 1);
    const int bkh = (lane & 8);

    for (int kt = 0; kt < 32; kt++) {
        __syncthreads();
        sts_tile<64, 16, 72>(kreg, sKh, sKl, tid);
        sts_tile<64, 16, 72>(vreg, sVh, sVl, tid);
        __syncthreads();
        if (kt < 31) {
            ldg_tile<64, 16>(kreg, kp, DKH, (size_t)(kt + 1) * 64, 0, tid);
            ldg_tile<64, 16>(vreg, vt, TT, 0, (kt + 1) * 64, tid);
        }

        float acc_s[1][8][4] = {};
        mma_hl<1, 8, 72, 72>(sQh, sQl, sKh, sKl, wrow, 0, lane, 0, 0, acc_s);
        mma_hl<1, 8, 72, 72>(sQh, sQl, sKh, sKl, wrow, 0, lane, 32, 32, acc_s);

        // epilogue: exp + mask, write unnormalized p, accumulate row sums
        #pragma unroll
        for (int hf = 0; hf < 2; hf++) {
            int tq = tile_m + wrow + rq + hf * 8;
            const u32* mrow = g_mbits + ((size_t)b * TT + tq) * (TT / 32);
            float* prow = aw + ((size_t)bz * TT + tq) * TT;
            #pragma unroll
            for (int nf = 0; nf < 8; nf++) {
                int tk = kt * 64 + cq + nf * 8;
                u32 w = mrow[tk >> 5];
                int sh = tk & 31;
                float e0 = acc_s[0][nf][hf * 2]     * 0.125f;
                float e1 = acc_s[0][nf][hf * 2 + 1] * 0.125f;
                float p0 = ((w >> sh) & 1u)       ? __expf(e0) : 0.0f;
                float p1 = ((w >> (sh + 1)) & 1u) ? __expf(e1) : 0.0f;
                rs[hf] += p0 + p1;
                *(float2*)&prow[tk] = make_float2(p0, p1);
                acc_s[0][nf][hf * 2]     = p0;
                acc_s[0][nf][hf * 2 + 1] = p1;
            }
        }

        // AV accumulate: P fragments built DIRECTLY from acc_s registers.
        #pragma unroll
        for (int j = 0; j < 4; j++) {
            u32 ah[4], al[4];
            #pragma unroll
            for (int b2 = 0; b2 < 2; b2++) {
                int nf = 2 * j + b2;
                __nv_bfloat16 h0, l0, h1, l1, h2, l2, h3, l3;
                split_hl(acc_s[0][nf][0], h0, l0);
                split_hl(acc_s[0][nf][1], h1, l1);
                split_hl(acc_s[0][nf][2], h2, l2);
                split_hl(acc_s[0][nf][3], h3, l3);
                ah[b2 * 2]     = pack2(h0, h1);
                ah[b2 * 2 + 1] = pack2(h2, h3);
                al[b2 * 2]     = pack2(l0, l1);
                al[b2 * 2 + 1] = pack2(l2, l3);
            }
            #pragma unroll
            for (int np = 0; np < 4; np++) {
                u32 bh0, bh1, bh2, bh3, bl0, bl1, bl2, bl3;
                ldsm_x4(bh0, bh1, bh2, bh3,
                        smem_u32(&sVh[brow_v + np * 16][j * 16 + bkh]));
                ldsm_x4(bl0, bl1, bl2, bl3,
                        smem_u32(&sVl[brow_v + np * 16][j * 16 + bkh]));
                mma16816(acc_av[2 * np],     ah, bh0, bh1);
                mma16816(acc_av[2 * np],     ah, bl0, bl1);
                mma16816(acc_av[2 * np],     al, bh0, bh1);
                mma16816(acc_av[2 * np + 1], ah, bh2, bh3);
                mma16816(acc_av[2 * np + 1], ah, bl2, bl3);
                mma16816(acc_av[2 * np + 1], al, bh2, bh3);
            }
        }
    }

    // deterministic row-sum reduction across the 4 lanes sharing each row
    #pragma unroll
    for (int hf = 0; hf < 2; hf++) {
        rs[hf] += __shfl_xor_sync(0xffffffffu, rs[hf], 1);
        rs[hf] += __shfl_xor_sync(0xffffffffu, rs[hf], 2);
    }
    float inv0 = 1.0f / rs[0], inv1 = 1.0f / rs[1];

    // write normalized ctx
    #pragma unroll
    for (int hf = 0; hf < 2; hf++) {
        float inv = hf ? inv1 : inv0;
        int tq = tile_m + wrow + rq + hf * 8;
        float* crow = g_ctx + ((size_t)b * TT + tq) * DDIM + hh * DKH;
        #pragma unroll
        for (int nf = 0; nf < 8; nf++) {
            int dk = cq + nf * 8;
            *(float2*)&crow[dk] = make_float2(acc_av[nf][hf * 2] * inv,
                                              acc_av[nf][hf * 2 + 1] * inv);
        }
    }
}

// ---------------- normalize: aw[row] /= sum(aw[row]) (deterministic) --------
__global__ __launch_bounds__(256) void norm_kernel(float* __restrict__ aw)
{
    __shared__ float reds[8];
    float* p = aw + (size_t)blockIdx.x * TT;
    const int tid = threadIdx.x, lane = tid & 31, wid = tid >> 5;

    float4 v0 = ((const float4*)p)[tid];
    float4 v1 = ((const float4*)p)[tid + 256];
    float s = v0.x + v0.y + v0.z + v0.w + v1.x + v1.y + v1.z + v1.w;
    #pragma unroll
    for (int o = 16; o > 0; o >>= 1) s += __shfl_xor_sync(0xffffffffu, s, o);
    if (lane == 0) reds[wid] = s;
    __syncthreads();
    float t = reds[0];
    #pragma unroll
    for (int i = 1; i < 8; i++) t += reds[i];
    float inv = 1.0f / t;
    v0.x *= inv; v0.y *= inv; v0.z *= inv; v0.w *= inv;
    v1.x *= inv; v1.y *= inv; v1.z *= inv; v1.w *= inv;
    ((float4*)p)[tid] = v0;
    ((float4*)p)[tid + 256] = v1;
}

// ---------------- outproj: out = ctx @ Wo^T + bo -> fp32 d_out --------------
__global__ __launch_bounds__(256, 2) void outproj_mma(const float* __restrict__ Wo,
                                                      const float* __restrict__ bo,
                                                      float* __restrict__ out)
{
    __shared__ __nv_bfloat16 sAh[128][40], sAl[128][40];
    __shared__ __nv_bfloat16 sBh[128][40], sBl[128][40];
    const int tid = threadIdx.x, lane = tid & 31, wid = tid >> 5;
    const int wrow = (wid >> 1) * 32, wcol = (wid & 1) * 64;
    const int tile_m = blockIdx.y * 128, tile_n = blockIdx.x * 128;

    float4 areg[4], breg[4];
    ldg_tile<128, 8>(areg, g_ctx, DDIM, tile_m, 0, tid);
    ldg_tile<128, 8>(breg, Wo, DDIM, tile_n, 0, tid);

    float acc[2][8][4] = {};
    for (int k0 = 0; k0 < DDIM; k0 += 32) {
        __syncthreads();
        sts_tile<128, 8, 40>(areg, sAh, sAl, tid);
        sts_tile<128, 8, 40>(breg, sBh, sBl, tid);
        __syncthreads();
        if (k0 + 32 < DDIM) {
            ldg_tile<128, 8>(areg, g_ctx, DDIM, tile_m, k0 + 32, tid);
            ldg_tile<128, 8>(breg, Wo, DDIM, tile_n, k0 + 32, tid);
        }
        mma_hl<2, 8, 40, 40>(sAh, sAl, sBh, sBl, wrow, wcol, lane, 0, 0, acc);
    }

    const int r0 = tile_m + wrow + (lane >> 2);
    const int c0 = tile_n + wcol + (lane & 3) * 2;
    #pragma unroll
    for (int mf = 0; mf < 2; mf++)
        #pragma unroll
        for (int hf = 0; hf < 2; hf++) {
            int m = r0 + mf * 16 + hf * 8;
            #pragma unroll
            for (int nf = 0; nf < 8; nf++) {
                int n = c0 + nf * 8;
                *(float2*)&out[(size_t)m * DDIM + n] =
                    make_float2(acc[mf][nf][hf * 2] + bo[n],
                                acc[mf][nf][hf * 2 + 1] + bo[n + 1]);
            }
        }
}

// -----------------------------------------------------------------------------
extern "C" void kernel_launch(void* const* d_in, const int* in_sizes, int n_in,
                              void* d_out, int out_size)
{
    const float* key   = (const float*)d_in[0];
    const float* value = (const float*)d_in[1];
    const float* query = (const float*)d_in[2];
    const int*   mask  = (const int*)d_in[3];
    const float* Wk = (const float*)d_in[4];
    const float* bk = (const float*)d_in[5];
    const float* Wv = (const float*)d_in[6];
    const float* bv = (const float*)d_in[7];
    const float* Wq = (const float*)d_in[8];
    const float* bq = (const float*)d_in[9];
    const float* Wo = (const float*)d_in[10];
    const float* bo = (const float*)d_in[11];

    float* out = (float*)d_out;
    float* ctx_out = out;                            // [B, T, D]
    float* aw_out  = out + (size_t)BB * TT * DDIM;   // [B, H, T, T]

    cvt_mask_kernel<<<((size_t)BB * TT * TT) / 256, 256>>>(mask);

    dim3 gp(DDIM / 128, (BB * TT) / 128);
    proj_mma<<<gp, 256>>>(query, Wq, bq, 0);
    proj_mma<<<gp, 256>>>(key,   Wk, bk, 1);
    proj_mma<<<gp, 256>>>(value, Wv, bv, 2);

    // fused attention: register-direct P->AV + pipelined KV loads
    const int FUSED_SMEM = 73728;
    cudaFuncSetAttribute(fused_attn, cudaFuncAttributeMaxDynamicSharedMemorySize,
                         FUSED_SMEM);
    fused_attn<<<dim3(TT / 128, BB * HH), 256, FUSED_SMEM>>>(aw_out);

    norm_kernel<<<BB * HH * TT, 256>>>(aw_out);

    outproj_mma<<<gp, 256>>>(Wo, bo, ctx_out);
}

// round 17
// speedup vs baseline: 1.1461x; 1.1461x over previous
#include <cuda_runtime.h>
#include <cuda_bf16.h>
#include <cstdint>

typedef unsigned int u32;

#define BB 4
#define TT 2048
#define DDIM 512
#define HH 8
#define DKH 64

#define SZQ ((size_t)BB * HH * TT * DKH)   // 4,194,304
#define SZX ((size_t)BB * TT * DDIM)       // 4,194,304

// ---------------- scratch (__device__ globals; no allocation) ----------------
__device__ float g_q[SZQ];                        // [B,H,T,DK] fp32
__device__ float g_k[SZQ];                        // [B,H,T,DK] fp32
__device__ float g_vt[SZQ];                       // [B,H,DK,T] fp32 (transposed)
__device__ float g_ctx[SZX];                      // [B,T,D] fp32
__device__ u32 g_mbits[(size_t)BB * TT * (TT / 32)];  // packed mask bits

// ---------------- helpers ----------------
__device__ __forceinline__ u32 smem_u32(const void* p) {
    u32 a;
    asm("{ .reg .u64 t; cvta.to.shared.u64 t, %1; cvt.u32.u64 %0, t; }" : "=r"(a) : "l"(p));
    return a;
}
__device__ __forceinline__ void split_hl(float v, __nv_bfloat16& h, __nv_bfloat16& l) {
    h = __float2bfloat16(v);
    l = __float2bfloat16(v - __bfloat162float(h));
}
__device__ __forceinline__ u32 pack2(__nv_bfloat16 a, __nv_bfloat16 b) {
    return (u32)__bfloat16_as_ushort(a) | ((u32)__bfloat16_as_ushort(b) << 16);
}
__device__ __forceinline__ void ldsm_x4(u32& r0, u32& r1, u32& r2, u32& r3, u32 addr) {
    asm volatile("ldmatrix.sync.aligned.m8n8.x4.shared.b16 {%0,%1,%2,%3}, [%4];"
                 : "=r"(r0), "=r"(r1), "=r"(r2), "=r"(r3) : "r"(addr));
}
__device__ __forceinline__ void mma16816(float* c, const u32* a, u32 b0, u32 b1) {
    asm volatile(
        "mma.sync.aligned.m16n8k16.row.col.f32.bf16.bf16.f32 "
        "{%0,%1,%2,%3}, {%4,%5,%6,%7}, {%8,%9}, {%0,%1,%2,%3};"
        : "+f"(c[0]), "+f"(c[1]), "+f"(c[2]), "+f"(c[3])
        : "r"(a[0]), "r"(a[1]), "r"(a[2]), "r"(a[3]), "r"(b0), "r"(b1));
}

// fp32 source [rows][ld] -> bf16 hi/lo smem tiles. W4 float4-groups per row.
template <int ROWS, int W4, int STRIDE>
__device__ __forceinline__ void load_f32_hl(
    __nv_bfloat16 (*sh)[STRIDE], __nv_bfloat16 (*sl)[STRIDE],
    const float* __restrict__ g, size_t ld, size_t row0, int k0, int tid)
{
    #pragma unroll
    for (int i = tid; i < ROWS * W4; i += 256) {
        int r = i / W4, c = i % W4;
        float4 v = *(const float4*)&g[(row0 + (size_t)r) * ld + k0 + c * 4];
        __nv_bfloat16 h0, l0, h1, l1, h2, l2, h3, l3;
        split_hl(v.x, h0, l0); split_hl(v.y, h1, l1);
        split_hl(v.z, h2, l2); split_hl(v.w, h3, l3);
        *(uint2*)&sh[r][c * 4] = make_uint2(pack2(h0, h1), pack2(h2, h3));
        *(uint2*)&sl[r][c * 4] = make_uint2(pack2(l0, l1), pack2(l2, l3));
    }
}

// warp-MMA over one 32-wide K slab, bf16x3 emulation (3 MMA terms).
// MMA issue order INTERLEAVES accumulators: same-acc reuse distance is
// 2*MF instructions (was 1), breaking RAW chains under asm-volatile ordering.
// Per-accumulator term order unchanged (hh, hl, lh) -> bit-identical results.
template <int MF, int NF, int AS, int BS>
__device__ __forceinline__ void mma_hl(
    const __nv_bfloat16 (*Ah)[AS], const __nv_bfloat16 (*Al)[AS],
    const __nv_bfloat16 (*Bh)[BS], const __nv_bfloat16 (*Bl)[BS],
    int wrow, int wcol, int lane, int kA, int kB, float acc[MF][NF][4])
{
    const int arow = wrow + (lane & 15);
    const int akh = (lane >> 4) << 3;
    const int brow = wcol + (lane & 7) + ((lane & 16) >> 1);
    const int bkh = (lane & 8);
    #pragma unroll
    for (int ks = 0; ks < 32; ks += 16) {
        u32 ah[MF][4], al[MF][4];
        #pragma unroll
        for (int mf = 0; mf < MF; mf++) {
            ldsm_x4(ah[mf][0], ah[mf][1], ah[mf][2], ah[mf][3],
                    smem_u32(&Ah[arow + mf * 16][kA + ks + akh]));
            ldsm_x4(al[mf][0], al[mf][1], al[mf][2], al[mf][3],
                    smem_u32(&Al[arow + mf * 16][kA + ks + akh]));
        }
        #pragma unroll
        for (int np = 0; np < NF / 2; np++) {
            u32 bh0, bh1, bh2, bh3, bl0, bl1, bl2, bl3;
            ldsm_x4(bh0, bh1, bh2, bh3, smem_u32(&Bh[brow + np * 16][kB + ks + bkh]));
            ldsm_x4(bl0, bl1, bl2, bl3, smem_u32(&Bl[brow + np * 16][kB + ks + bkh]));
            // term hh
            #pragma unroll
            for (int mf = 0; mf < MF; mf++) {
                mma16816(acc[mf][2 * np],     ah[mf], bh0, bh1);
                mma16816(acc[mf][2 * np + 1], ah[mf], bh2, bh3);
            }
            // term hl
            #pragma unroll
            for (int mf = 0; mf < MF; mf++) {
                mma16816(acc[mf][2 * np],     ah[mf], bl0, bl1);
                mma16816(acc[mf][2 * np + 1], ah[mf], bl2, bl3);
            }
            // term lh
            #pragma unroll
            for (int mf = 0; mf < MF; mf++) {
                mma16816(acc[mf][2 * np],     al[mf], bh0, bh1);
                mma16816(acc[mf][2 * np + 1], al[mf], bh2, bh3);
            }
        }
    }
}

// ---------------- mask bit packing ----------------
__global__ __launch_bounds__(256) void cvt_mask_kernel(const int* __restrict__ mask)
{
    size_t i = (size_t)blockIdx.x * 256 + threadIdx.x;
    u32 bit = (mask[i] != 0) ? 1u : 0u;
    u32 word = __ballot_sync(0xffffffffu, bit);
    if ((threadIdx.x & 31) == 0) g_mbits[i >> 5] = word;
}

// ---------------- proj: out = X @ W^T + b -> q/k fp32 [B,H,T,DK], vt [B,H,DK,T]
__global__ __launch_bounds__(256, 2) void proj_mma(const float* __restrict__ X,
                                                   const float* __restrict__ W,
                                                   const float* __restrict__ bias, int dst)
{
    __shared__ __nv_bfloat16 sAh[128][40], sAl[128][40];
    __shared__ __nv_bfloat16 sBh[128][40], sBl[128][40];
    const int tid = threadIdx.x, lane = tid & 31, wid = tid >> 5;
    const int wrow = (wid >> 1) * 32, wcol = (wid & 1) * 64;
    const int tile_m = blockIdx.y * 128, tile_n = blockIdx.x * 128;

    float acc[2][8][4] = {};
    for (int k0 = 0; k0 < DDIM; k0 += 32) {
        __syncthreads();
        load_f32_hl<128, 8, 40>(sAh, sAl, X, DDIM, tile_m, k0, tid);
        load_f32_hl<128, 8, 40>(sBh, sBl, W, DDIM, tile_n, k0, tid);
        __syncthreads();
        mma_hl<2, 8, 40, 40>(sAh, sAl, sBh, sBl, wrow, wcol, lane, 0, 0, acc);
    }

    float* dq = (dst == 0) ? g_q : g_k;
    const int r0 = tile_m + wrow + (lane >> 2);
    const int c0 = tile_n + wcol + (lane & 3) * 2;
    #pragma unroll
    for (int mf = 0; mf < 2; mf++)
        #pragma unroll
        for (int hf = 0; hf < 2; hf++) {
            int m = r0 + mf * 16 + hf * 8;
            int b = m >> 11, t = m & (TT - 1);
            #pragma unroll
            for (int nf = 0; nf < 8; nf++) {
                int n = c0 + nf * 8;
                float v0 = acc[mf][nf][hf * 2]     + bias[n];
                float v1 = acc[mf][nf][hf * 2 + 1] + bias[n + 1];
                int hh = n >> 6, dk = n & 63;
                if (dst == 2) {
                    size_t base = ((size_t)(b * HH + hh) * DKH + dk) * TT + t;
                    g_vt[base] = v0;
                    g_vt[base + TT] = v1;
                } else {
                    size_t idx = ((size_t)(b * HH + hh) * TT + t) * DKH + dk;
                    *(float2*)&dq[idx] = make_float2(v0, v1);
                }
            }
        }
}

// ---------------- fused: S=QK^T/8 -> exp/mask -> p(unnorm)->aw ;
// ctx=(p@v)/sum via REGISTER-direct P fragments (no smem staging).
// grid (16 tile_m, 32 bh), 256 thr, dynamic smem 73728 B
__global__ __launch_bounds__(256, 2) void fused_attn(float* __restrict__ aw)
{
    extern __shared__ __nv_bfloat16 dyn[];
    __nv_bfloat16 (*sQh)[72] = (__nv_bfloat16 (*)[72])(dyn);
    __nv_bfloat16 (*sQl)[72] = (__nv_bfloat16 (*)[72])(dyn + 9216);
    __nv_bfloat16 (*sKh)[72] = (__nv_bfloat16 (*)[72])(dyn + 18432);
    __nv_bfloat16 (*sKl)[72] = (__nv_bfloat16 (*)[72])(dyn + 23040);
    __nv_bfloat16 (*sVh)[72] = (__nv_bfloat16 (*)[72])(dyn + 27648);
    __nv_bfloat16 (*sVl)[72] = (__nv_bfloat16 (*)[72])(dyn + 32256);

    const int tid = threadIdx.x, lane = tid & 31, wid = tid >> 5;
    const int wrow = wid * 16;
    const int tile_m = blockIdx.x * 128;
    const int bz = blockIdx.y;
    const int b = bz >> 3, hh = bz & 7;
    const float* qp = g_q + (size_t)bz * TT * DKH;
    const float* kp = g_k + (size_t)bz * TT * DKH;
    const float* vt = g_vt + (size_t)bz * DKH * TT;

    load_f32_hl<128, 16, 72>(sQh, sQl, qp, DKH, tile_m, 0, tid);

    float acc_av[8][4] = {};
    float rs[2] = {0.0f, 0.0f};
    const int rq = (lane >> 2);
    const int cq = (lane & 3) * 2;
    // B-fragment addressing for V (wcol = 0)
    const int brow_v = (lane & 7) + ((lane & 16) >> 1);
    const int bkh = (lane & 8);

    for (int kt = 0; kt < 32; kt++) {
        __syncthreads();
        load_f32_hl<64, 16, 72>(sKh, sKl, kp, DKH, kt * 64, 0, tid);
        load_f32_hl<64, 16, 72>(sVh, sVl, vt, TT, 0, kt * 64, tid);
        __syncthreads();

        float acc_s[1][8][4] = {};
        mma_hl<1, 8, 72, 72>(sQh, sQl, sKh, sKl, wrow, 0, lane, 0, 0, acc_s);
        mma_hl<1, 8, 72, 72>(sQh, sQl, sKh, sKl, wrow, 0, lane, 32, 32, acc_s);

        // epilogue: exp + mask, write unnormalized p, accumulate row sums
        #pragma unroll
        for (int hf = 0; hf < 2; hf++) {
            int tq = tile_m + wrow + rq + hf * 8;
            const u32* mrow = g_mbits + ((size_t)b * TT + tq) * (TT / 32);
            float* prow = aw + ((size_t)bz * TT + tq) * TT;
            #pragma unroll
            for (int nf = 0; nf < 8; nf++) {
                int tk = kt * 64 + cq + nf * 8;
                u32 w = mrow[tk >> 5];
                int sh = tk & 31;
                float e0 = acc_s[0][nf][hf * 2]     * 0.125f;
                float e1 = acc_s[0][nf][hf * 2 + 1] * 0.125f;
                float p0 = ((w >> sh) & 1u)       ? __expf(e0) : 0.0f;
                float p1 = ((w >> (sh + 1)) & 1u) ? __expf(e1) : 0.0f;
                rs[hf] += p0 + p1;
                *(float2*)&prow[tk] = make_float2(p0, p1);
                acc_s[0][nf][hf * 2]     = p0;
                acc_s[0][nf][hf * 2 + 1] = p1;
            }
        }

        // AV accumulate: P fragments built DIRECTLY from acc_s registers.
        // MMA order interleaves the two accumulator bands (distance 2).
        #pragma unroll
        for (int j = 0; j < 4; j++) {
            u32 ah[4], al[4];
            #pragma unroll
            for (int b2 = 0; b2 < 2; b2++) {
                int nf = 2 * j + b2;
                __nv_bfloat16 h0, l0, h1, l1, h2, l2, h3, l3;
                split_hl(acc_s[0][nf][0], h0, l0);
                split_hl(acc_s[0][nf][1], h1, l1);
                split_hl(acc_s[0][nf][2], h2, l2);
                split_hl(acc_s[0][nf][3], h3, l3);
                ah[b2 * 2]     = pack2(h0, h1);
                ah[b2 * 2 + 1] = pack2(h2, h3);
                al[b2 * 2]     = pack2(l0, l1);
                al[b2 * 2 + 1] = pack2(l2, l3);
            }
            #pragma unroll
            for (int np = 0; np < 4; np++) {
                u32 bh0, bh1, bh2, bh3, bl0, bl1, bl2, bl3;
                ldsm_x4(bh0, bh1, bh2, bh3,
                        smem_u32(&sVh[brow_v + np * 16][j * 16 + bkh]));
                ldsm_x4(bl0, bl1, bl2, bl3,
                        smem_u32(&sVl[brow_v + np * 16][j * 16 + bkh]));
                mma16816(acc_av[2 * np],     ah, bh0, bh1);
                mma16816(acc_av[2 * np + 1], ah, bh2, bh3);
                mma16816(acc_av[2 * np],     ah, bl0, bl1);
                mma16816(acc_av[2 * np + 1], ah, bl2, bl3);
                mma16816(acc_av[2 * np],     al, bh0, bh1);
                mma16816(acc_av[2 * np + 1], al, bh2, bh3);
            }
        }
    }

    // deterministic row-sum reduction across the 4 lanes sharing each row
    #pragma unroll
    for (int hf = 0; hf < 2; hf++) {
        rs[hf] += __shfl_xor_sync(0xffffffffu, rs[hf], 1);
        rs[hf] += __shfl_xor_sync(0xffffffffu, rs[hf], 2);
    }
    float inv0 = 1.0f / rs[0], inv1 = 1.0f / rs[1];

    // write normalized ctx
    #pragma unroll
    for (int hf = 0; hf < 2; hf++) {
        float inv = hf ? inv1 : inv0;
        int tq = tile_m + wrow + rq + hf * 8;
        float* crow = g_ctx + ((size_t)b * TT + tq) * DDIM + hh * DKH;
        #pragma unroll
        for (int nf = 0; nf < 8; nf++) {
            int dk = cq + nf * 8;
            *(float2*)&crow[dk] = make_float2(acc_av[nf][hf * 2] * inv,
                                              acc_av[nf][hf * 2 + 1] * inv);
        }
    }
}

// ---------------- normalize: aw[row] /= sum(aw[row]) (deterministic) --------
__global__ __launch_bounds__(256) void norm_kernel(float* __restrict__ aw)
{
    __shared__ float reds[8];
    float* p = aw + (size_t)blockIdx.x * TT;
    const int tid = threadIdx.x, lane = tid & 31, wid = tid >> 5;

    float4 v0 = ((const float4*)p)[tid];
    float4 v1 = ((const float4*)p)[tid + 256];
    float s = v0.x + v0.y + v0.z + v0.w + v1.x + v1.y + v1.z + v1.w;
    #pragma unroll
    for (int o = 16; o > 0; o >>= 1) s += __shfl_xor_sync(0xffffffffu, s, o);
    if (lane == 0) reds[wid] = s;
    __syncthreads();
    float t = reds[0];
    #pragma unroll
    for (int i = 1; i < 8; i++) t += reds[i];
    float inv = 1.0f / t;
    v0.x *= inv; v0.y *= inv; v0.z *= inv; v0.w *= inv;
    v1.x *= inv; v1.y *= inv; v1.z *= inv; v1.w *= inv;
    ((float4*)p)[tid] = v0;
    ((float4*)p)[tid + 256] = v1;
}

// ---------------- outproj: out = ctx @ Wo^T + bo -> fp32 d_out --------------
__global__ __launch_bounds__(256, 2) void outproj_mma(const float* __restrict__ Wo,
                                                      const float* __restrict__ bo,
                                                      float* __restrict__ out)
{
    __shared__ __nv_bfloat16 sAh[128][40], sAl[128][40];
    __shared__ __nv_bfloat16 sBh[128][40], sBl[128][40];
    const int tid = threadIdx.x, lane = tid & 31, wid = tid >> 5;
    const int wrow = (wid >> 1) * 32, wcol = (wid & 1) * 64;
    const int tile_m = blockIdx.y * 128, tile_n = blockIdx.x * 128;

    float acc[2][8][4] = {};
    for (int k0 = 0; k0 < DDIM; k0 += 32) {
        __syncthreads();
        load_f32_hl<128, 8, 40>(sAh, sAl, g_ctx, DDIM, tile_m, k0, tid);
        load_f32_hl<128, 8, 40>(sBh, sBl, Wo, DDIM, tile_n, k0, tid);
        __syncthreads();
        mma_hl<2, 8, 40, 40>(sAh, sAl, sBh, sBl, wrow, wcol, lane, 0, 0, acc);
    }

    const int r0 = tile_m + wrow + (lane >> 2);
    const int c0 = tile_n + wcol + (lane & 3) * 2;
    #pragma unroll
    for (int mf = 0; mf < 2; mf++)
        #pragma unroll
        for (int hf = 0; hf < 2; hf++) {
            int m = r0 + mf * 16 + hf * 8;
            #pragma unroll
            for (int nf = 0; nf < 8; nf++) {
                int n = c0 + nf * 8;
                *(float2*)&out[(size_t)m * DDIM + n] =
                    make_float2(acc[mf][nf][hf * 2] + bo[n],
                                acc[mf][nf][hf * 2 + 1] + bo[n + 1]);
            }
        }
}

// -----------------------------------------------------------------------------
extern "C" void kernel_launch(void* const* d_in, const int* in_sizes, int n_in,
                              void* d_out, int out_size)
{
    const float* key   = (const float*)d_in[0];
    const float* value = (const float*)d_in[1];
    const float* query = (const float*)d_in[2];
    const int*   mask  = (const int*)d_in[3];
    const float* Wk = (const float*)d_in[4];
    const float* bk = (const float*)d_in[5];
    const float* Wv = (const float*)d_in[6];
    const float* bv = (const float*)d_in[7];
    const float* Wq = (const float*)d_in[8];
    const float* bq = (const float*)d_in[9];
    const float* Wo = (const float*)d_in[10];
    const float* bo = (const float*)d_in[11];

    float* out = (float*)d_out;
    float* ctx_out = out;                            // [B, T, D]
    float* aw_out  = out + (size_t)BB * TT * DDIM;   // [B, H, T, T]

    cvt_mask_kernel<<<((size_t)BB * TT * TT) / 256, 256>>>(mask);

    dim3 gp(DDIM / 128, (BB * TT) / 128);
    proj_mma<<<gp, 256>>>(query, Wq, bq, 0);
    proj_mma<<<gp, 256>>>(key,   Wk, bk, 1);
    proj_mma<<<gp, 256>>>(value, Wv, bv, 2);

    // fused attention: register-direct P->AV, interleaved MMA issue order
    const int FUSED_SMEM = 73728;
    cudaFuncSetAttribute(fused_attn, cudaFuncAttributeMaxDynamicSharedMemorySize,
                         FUSED_SMEM);
    fused_attn<<<dim3(TT / 128, BB * HH), 256, FUSED_SMEM>>>(aw_out);

    norm_kernel<<<BB * HH * TT, 256>>>(aw_out);

    outproj_mma<<<gp, 256>>>(Wo, bo, ctx_out);
}